// round 10
// baseline (speedup 1.0000x reference)
#include <cuda_runtime.h>
#include <cuda_bf16.h>
#include <cstdint>

#define EPSV 1e-5f

// ---- smem map (bytes), tiles XOR-swizzled (chunk16B ^= row&7) ----
#define XL_O   0            // [256 c][64 n] bf16 hi, pitch 128B
#define XL_LO  32768
#define CK_O   65536        // [64 k][256 c] bf16 hi, pitch 512B
#define CK_LO  98304
#define CV_O   131072       // [256 c][64 k] bf16 hi, pitch 128B
#define CV_LO  163840
#define ATT_O  196608       // [64 k][64 n] bf16 hi, pitch 128B
#define ATT_LO 204800
#define WMAX_O 212992       // [4][64] f32
#define WSUM_O 214016       // [4][64] f32
#define KB_O   215040       // [64] f32
#define INV_O  215296       // [64] f32
#define SMEMSZ 215552

__device__ float g_p[8 * 128 * 64];
__device__ float g_ck[8 * 64 * 256];   // [b][k][c]
__device__ float g_cv[8 * 256 * 64];   // [b][c][k]

__device__ __forceinline__ uint32_t s2u(const void* p) {
    uint32_t a; asm("{.reg .u64 t; cvta.to.shared.u64 t,%1; cvt.u32.u64 %0,t;}" : "=r"(a) : "l"(p)); return a;
}
__device__ __forceinline__ void ldsm4(uint32_t* r, uint32_t a) {
    asm volatile("ldmatrix.sync.aligned.m8n8.x4.shared.b16 {%0,%1,%2,%3},[%4];"
                 : "=r"(r[0]), "=r"(r[1]), "=r"(r[2]), "=r"(r[3]) : "r"(a));
}
__device__ __forceinline__ void ldsm4t(uint32_t* r, uint32_t a) {
    asm volatile("ldmatrix.sync.aligned.m8n8.x4.trans.shared.b16 {%0,%1,%2,%3},[%4];"
                 : "=r"(r[0]), "=r"(r[1]), "=r"(r[2]), "=r"(r[3]) : "r"(a));
}
__device__ __forceinline__ void hmma(float* d, const uint32_t* a, const uint32_t* b) {
    asm volatile("mma.sync.aligned.m16n8k16.row.col.f32.bf16.bf16.f32 "
                 "{%0,%1,%2,%3},{%4,%5,%6,%7},{%8,%9},{%0,%1,%2,%3};"
                 : "+f"(d[0]), "+f"(d[1]), "+f"(d[2]), "+f"(d[3])
                 : "r"(a[0]), "r"(a[1]), "r"(a[2]), "r"(a[3]), "r"(b[0]), "r"(b[1]));
}
__device__ __forceinline__ uint32_t bpack(float x, float y) {
    __nv_bfloat162 h = __floats2bfloat162_rn(x, y);
    return *(uint32_t*)&h;
}
__device__ __forceinline__ float2 bunpack(uint32_t u) {
    __nv_bfloat162 h = *(__nv_bfloat162*)&u;
    return __bfloat1622float2(h);
}

// ================= Kernel 1: BN(x_h) + 8x8 maxpool =================
__global__ __launch_bounds__(256) void pool_kernel(
    const float* __restrict__ x_h, const float* __restrict__ gam, const float* __restrict__ bet,
    const float* __restrict__ mu, const float* __restrict__ var)
{
    int idx = blockIdx.x * 256 + threadIdx.x;
    int k = idx & 63, c = (idx >> 6) & 127, b = idx >> 13;
    float scl = gam[c] * rsqrtf(var[c] + EPSV);
    float bia = bet[c] - mu[c] * scl;
    const float* base = x_h + ((((b * 128 + c) * 64) + (k >> 3) * 8) * 64) + (k & 7) * 8;
    float mx = -3.4e38f, mn = 3.4e38f;
#pragma unroll
    for (int r = 0; r < 8; r++) {
        const float4* p4 = (const float4*)(base + r * 64);
        float4 a = p4[0], d = p4[1];
        mx = fmaxf(mx, fmaxf(fmaxf(a.x, a.y), fmaxf(a.z, a.w)));
        mx = fmaxf(mx, fmaxf(fmaxf(d.x, d.y), fmaxf(d.z, d.w)));
        mn = fminf(mn, fminf(fminf(a.x, a.y), fminf(a.z, a.w)));
        mn = fminf(mn, fminf(fminf(d.x, d.y), fminf(d.z, d.w)));
    }
    g_p[idx] = ((scl >= 0.f) ? mx : mn) * scl + bia;
}

// ================= Kernel 2: 1x1 conv -> g_ck [b][k][c] / g_cv [b][c][k] ==========
__global__ __launch_bounds__(256) void kv_kernel(
    const float* __restrict__ kv_w, const float* __restrict__ kv_b)
{
    extern __shared__ float sm2[];
    float* sW = sm2; float* sP = sm2 + 8192;
    int og = blockIdx.x, b = blockIdx.y, t = threadIdx.x;
    const float4* wsrc = (const float4*)(kv_w + og * 64 * 128);
    const float4* psrc = (const float4*)(g_p + b * 8192);
#pragma unroll
    for (int i = 0; i < 8; i++) {
        ((float4*)sW)[t + i * 256] = wsrc[t + i * 256];
        ((float4*)sP)[t + i * 256] = psrc[t + i * 256];
    }
    __syncthreads();
    int ty = t >> 4, tx = t & 15;
    float acc[4][4] = {};
#pragma unroll 4
    for (int c = 0; c < 128; c++) {
        float4 pv = ((const float4*)(sP + c * 64))[tx];
#pragma unroll
        for (int i = 0; i < 4; i++) {
            float w = sW[(ty * 4 + i) * 128 + c];
            acc[i][0] += w * pv.x; acc[i][1] += w * pv.y;
            acc[i][2] += w * pv.z; acc[i][3] += w * pv.w;
        }
    }
#pragma unroll
    for (int i = 0; i < 4; i++) {
        int o = og * 64 + ty * 4 + i;
        float bs = kv_b[o];
#pragma unroll
        for (int j = 0; j < 4; j++) {
            int k = tx * 4 + j;
            float v = acc[i][j] + bs;
            if (o < 256) g_ck[(b * 64 + k) * 256 + o] = v;
            else         g_cv[(b * 256 + (o - 256)) * 64 + k] = v;
        }
    }
}

// ================= Kernel 3: persistent HMMA main (512 thr, 16 warps) =================
__global__ __launch_bounds__(512) void main_kernel(
    const float* __restrict__ x_l,
    const float* __restrict__ gam, const float* __restrict__ bet,
    const float* __restrict__ mu,  const float* __restrict__ var,
    const float* __restrict__ reatt, float* __restrict__ out)
{
    extern __shared__ __align__(128) char smc[];
    const uint32_t smb = s2u(smc);
    float* WMAX = (float*)(smc + WMAX_O);
    float* WSUM = (float*)(smc + WSUM_O);
    float* KB   = (float*)(smc + KB_O);
    float* INV  = (float*)(smc + INV_O);

    const int t = threadIdx.x, w = t >> 5, lane = t & 31;
    const int g8 = lane >> 2, tid4 = lane & 3;
    const int r8 = lane & 7, i4 = lane >> 3;
    const int bid = blockIdx.x;
    const int start = bid * 13 + (bid < 72 ? bid : 72);
    const int cnt = 13 + (bid < 72 ? 1 : 0);

    const int m0_2 = (w >> 2) * 16;   // phase2: k-row base
    const int n0_2 = (w & 3) * 16;    // phase2: n base
    const int m0_3 = w * 16;          // phase3: c base

    // preload first tile's x_l into registers (8 float4/thread)
    float4 pf[8];
    {
        int b0 = start >> 8, h0 = (start & 255) << 6;
        const float4* xs = (const float4*)(x_l + (long)b0 * 4194304 + h0);
#pragma unroll
        for (int i = 0; i < 8; i++) { int e = t + i * 512; pf[i] = __ldg(&xs[(long)(e >> 4) * 4096 + (e & 15)]); }
    }
    bool pf_valid = true;
    int cur_b = -1;

    for (int g = start; g < start + cnt; ++g) {
        const int b = g >> 8, hw0 = (g & 255) << 6;

        // ---- commit prefetched x_l -> XL hi/lo (swizzled) ----
        if (pf_valid) {
#pragma unroll
            for (int i = 0; i < 8; i++) {
                int e = t + i * 512, c = e >> 4, n4 = e & 15;
                float4 v = pf[i];
                uint32_t h01 = bpack(v.x, v.y), h23 = bpack(v.z, v.w);
                float2 f01 = bunpack(h01), f23 = bunpack(h23);
                uint32_t l01 = bpack(v.x - f01.x, v.y - f01.y);
                uint32_t l23 = bpack(v.z - f23.x, v.w - f23.y);
                int off = c * 128 + (((n4 >> 1) ^ (c & 7)) << 4) + (n4 & 1) * 8;
                *(uint2*)(smc + XL_O + off)  = make_uint2(h01, h23);
                *(uint2*)(smc + XL_LO + off) = make_uint2(l01, l23);
            }
            pf_valid = false;
        }

        // ---- per-batch restage: ck (BN-scaled, split), cv (split), kb ----
        if (b != cur_b) {
            cur_b = b;
            __syncthreads();
            float* SCL = (float*)(smc + ATT_O);
            float* BIA = (float*)(smc + ATT_O + 1024);
            if (t < 256) {
                float sc = gam[t] * rsqrtf(var[t] + EPSV);
                SCL[t] = sc; BIA[t] = bet[t] - mu[t] * sc;
            }
            __syncthreads();
            {   // ck: k = t>>3, 32 c's per thread
                int k = t >> 3, cq = (t & 7) * 32;
                const float* src = g_ck + (b * 64 + k) * 256;
#pragma unroll 4
                for (int cc = 0; cc < 32; cc += 4) {
                    int c = cq + cc;
                    float4 v = *(const float4*)(src + c);
                    v.x *= SCL[c] * 0.125f;   v.y *= SCL[c+1] * 0.125f;
                    v.z *= SCL[c+2] * 0.125f; v.w *= SCL[c+3] * 0.125f;
                    uint32_t h01 = bpack(v.x, v.y), h23 = bpack(v.z, v.w);
                    float2 f01 = bunpack(h01), f23 = bunpack(h23);
                    uint32_t l01 = bpack(v.x - f01.x, v.y - f01.y);
                    uint32_t l23 = bpack(v.z - f23.x, v.w - f23.y);
                    int off = k * 512 + (((c >> 3) ^ (k & 7)) << 4) + (c & 7) * 2;
                    *(uint2*)(smc + CK_O + off)  = make_uint2(h01, h23);
                    *(uint2*)(smc + CK_LO + off) = make_uint2(l01, l23);
                }
            }
            {   // cv: row c = t>>1, 32 k's per thread
                int c = t >> 1, ko = (t & 1) * 32;
                const float* sv = g_cv + (b * 256 + c) * 64;
#pragma unroll 4
                for (int kk = 0; kk < 32; kk += 4) {
                    int k = ko + kk;
                    float4 v = *(const float4*)(sv + k);
                    uint32_t h01 = bpack(v.x, v.y), h23 = bpack(v.z, v.w);
                    float2 f01 = bunpack(h01), f23 = bunpack(h23);
                    uint32_t l01 = bpack(v.x - f01.x, v.y - f01.y);
                    uint32_t l23 = bpack(v.z - f23.x, v.w - f23.y);
                    int off = c * 128 + (((k >> 3) ^ (c & 7)) << 4) + (k & 7) * 2;
                    *(uint2*)(smc + CV_O + off)  = make_uint2(h01, h23);
                    *(uint2*)(smc + CV_LO + off) = make_uint2(l01, l23);
                }
            }
            if (t < 256) {   // kb partials
                int kk = t & 63, q = t >> 6;
                const float* bp = g_ck + (b * 64 + kk) * 256 + q * 64;
                float s = 0.f;
#pragma unroll 16
                for (int c = 0; c < 64; c++) s += bp[c] * BIA[q * 64 + c];
                WMAX[q * 64 + kk] = s;
            }
            __syncthreads();
            if (t < 64) KB[t] = 0.125f * (WMAX[t] + WMAX[64 + t] + WMAX[128 + t] + WMAX[192 + t] + __ldg(reatt + t));
        }
        __syncthreads();

        // ================= Phase 2: logits = ck^T * xl (3 passes) =================
        float d2[2][4] = {};
        {
            const int arow = m0_2 + r8 + 8 * (i4 & 1);
            const int bro  = r8 + 8 * (i4 & 1);
            const int nch  = (n0_2 >> 3) + (i4 >> 1);
#pragma unroll 1
            for (int pass = 0; pass < 3; pass++) {
                uint32_t ab = smb + (pass == 1 ? CK_LO : CK_O) + arow * 512;
                uint32_t bb = smb + (pass == 2 ? XL_LO : XL_O);
#pragma unroll
                for (int s = 0; s < 16; s++) {
                    uint32_t a[4], bf[4];
                    ldsm4(a, ab + (((s * 2 + (i4 >> 1)) ^ r8) << 4));
                    ldsm4t(bf, bb + (s * 16 + bro) * 128 + ((nch ^ r8) << 4));
                    hmma(d2[0], a, bf); hmma(d2[1], a, bf + 2);
                }
            }
        }

        // ================= softmax (register-resident) =================
        {
            float kb0 = KB[m0_2 + g8], kb1 = KB[m0_2 + g8 + 8];
            float cm[2][2];
#pragma unroll
            for (int ns = 0; ns < 2; ns++) {
                d2[ns][0] += kb0; d2[ns][1] += kb0;
                d2[ns][2] += kb1; d2[ns][3] += kb1;
                cm[ns][0] = fmaxf(d2[ns][0], d2[ns][2]);
                cm[ns][1] = fmaxf(d2[ns][1], d2[ns][3]);
            }
#pragma unroll
            for (int st = 4; st < 32; st <<= 1)
#pragma unroll
                for (int ns = 0; ns < 2; ns++) {
                    cm[ns][0] = fmaxf(cm[ns][0], __shfl_xor_sync(0xffffffffu, cm[ns][0], st));
                    cm[ns][1] = fmaxf(cm[ns][1], __shfl_xor_sync(0xffffffffu, cm[ns][1], st));
                }
            if (g8 == 0)
#pragma unroll
                for (int ns = 0; ns < 2; ns++) {
                    int n = n0_2 + ns * 8 + tid4 * 2;
                    WMAX[(w >> 2) * 64 + n] = cm[ns][0];
                    WMAX[(w >> 2) * 64 + n + 1] = cm[ns][1];
                }
            __syncthreads();
            if (t < 64) WMAX[t] = fmaxf(fmaxf(WMAX[t], WMAX[64 + t]), fmaxf(WMAX[128 + t], WMAX[192 + t]));
            __syncthreads();

            float sm_[2][2];
            int k0r = m0_2 + g8;
#pragma unroll
            for (int ns = 0; ns < 2; ns++) {
                int n = n0_2 + ns * 8 + tid4 * 2;
                float c0 = WMAX[n], c1 = WMAX[n + 1];
                float e00 = __expf(d2[ns][0] - c0), e01 = __expf(d2[ns][1] - c1);
                float e10 = __expf(d2[ns][2] - c0), e11 = __expf(d2[ns][3] - c1);
                sm_[ns][0] = e00 + e10; sm_[ns][1] = e01 + e11;
                uint32_t h0 = bpack(e00, e01); float2 f0 = bunpack(h0);
                uint32_t l0 = bpack(e00 - f0.x, e01 - f0.y);
                uint32_t h1 = bpack(e10, e11); float2 f1 = bunpack(h1);
                uint32_t l1 = bpack(e10 - f1.x, e11 - f1.y);
                int off0 = k0r * 128 + (((n >> 3) ^ g8) << 4) + (n & 7) * 2;
                int off1 = off0 + 8 * 128;
                *(uint32_t*)(smc + ATT_O + off0)  = h0;
                *(uint32_t*)(smc + ATT_LO + off0) = l0;
                *(uint32_t*)(smc + ATT_O + off1)  = h1;
                *(uint32_t*)(smc + ATT_LO + off1) = l1;
            }
#pragma unroll
            for (int st = 4; st < 32; st <<= 1)
#pragma unroll
                for (int ns = 0; ns < 2; ns++) {
                    sm_[ns][0] += __shfl_xor_sync(0xffffffffu, sm_[ns][0], st);
                    sm_[ns][1] += __shfl_xor_sync(0xffffffffu, sm_[ns][1], st);
                }
            if (g8 == 0)
#pragma unroll
                for (int ns = 0; ns < 2; ns++) {
                    int n = n0_2 + ns * 8 + tid4 * 2;
                    WSUM[(w >> 2) * 64 + n] = sm_[ns][0];
                    WSUM[(w >> 2) * 64 + n + 1] = sm_[ns][1];
                }
            __syncthreads();
            if (t < 64) INV[t] = 1.f / (WSUM[t] + WSUM[64 + t] + WSUM[128 + t] + WSUM[192 + t]);
            __syncthreads();
        }

        // ================= Phase 3: out-acc = cv * att (3 passes) =================
        float d3[8][4] = {};
        {
            const int aro = m0_3 + r8 + 8 * (i4 & 1);
            const int bro = r8 + 8 * (i4 & 1);
#pragma unroll 1
            for (int pass = 0; pass < 3; pass++) {
                uint32_t ab = smb + (pass == 1 ? CV_LO : CV_O) + aro * 128;
                uint32_t bb = smb + (pass == 2 ? ATT_LO : ATT_O);
#pragma unroll
                for (int ks = 0; ks < 4; ks++) {
                    uint32_t bfr[4][4];
                    uint32_t br = bb + (ks * 16 + bro) * 128;
#pragma unroll
                    for (int nq = 0; nq < 4; nq++)
                        ldsm4t(bfr[nq], br + (((nq * 2 + (i4 >> 1)) ^ r8) << 4));
                    uint32_t a[4];
                    ldsm4(a, ab + (((ks * 2 + (i4 >> 1)) ^ r8) << 4));
#pragma unroll
                    for (int nq = 0; nq < 4; nq++) {
                        hmma(d3[nq * 2], a, bfr[nq]);
                        hmma(d3[nq * 2 + 1], a, bfr[nq] + 2);
                    }
                }
            }
        }

        // ---- prefetch next tile's x_l (hidden under epilogue) ----
        const bool has_next = (g + 1 < start + cnt);
        if (has_next) {
            int gn = g + 1, bn = gn >> 8, hn = (gn & 255) << 6;
            const float4* xs = (const float4*)(x_l + (long)bn * 4194304 + hn);
#pragma unroll
            for (int i = 0; i < 8; i++) { int e = t + i * 512; pf[i] = __ldg(&xs[(long)(e >> 4) * 4096 + (e & 15)]); }
            pf_valid = true;
        }

        // ================= epilogue: residual + 1/sum, direct STG =================
        {
            long gb = (long)b * 4194304 + hw0;
            int c0r = m0_3 + g8, c1r = c0r + 8;
#pragma unroll
            for (int nq2 = 0; nq2 < 8; nq2++) {
                int n = nq2 * 8 + tid4 * 2;
                float2 iv = *(float2*)(INV + n);
                int sw = ((n >> 3) ^ g8) << 4;
                int o0 = c0r * 128 + sw + (n & 7) * 2;
                int o1 = c1r * 128 + sw + (n & 7) * 2;
                float2 h0 = bunpack(*(uint32_t*)(smc + XL_O + o0));
                float2 l0 = bunpack(*(uint32_t*)(smc + XL_LO + o0));
                float2 h1 = bunpack(*(uint32_t*)(smc + XL_O + o1));
                float2 l1 = bunpack(*(uint32_t*)(smc + XL_LO + o1));
                float2 r0, r1;
                r0.x = h0.x + l0.x + d3[nq2][0] * iv.x;
                r0.y = h0.y + l0.y + d3[nq2][1] * iv.y;
                r1.x = h1.x + l1.x + d3[nq2][2] * iv.x;
                r1.y = h1.y + l1.y + d3[nq2][3] * iv.y;
                *(float2*)(out + gb + (long)c0r * 16384 + n) = r0;
                *(float2*)(out + gb + (long)c1r * 16384 + n) = r1;
            }
        }
        __syncthreads();
    }
}

// ============================================================
extern "C" void kernel_launch(void* const* d_in, const int* in_sizes, int n_in,
                              void* d_out, int out_size)
{
    const float* x_h = (const float*)d_in[0];
    const float* x_l = (const float*)d_in[1];
    const float* bhg = (const float*)d_in[2];
    const float* bhb = (const float*)d_in[3];
    const float* bhm = (const float*)d_in[4];
    const float* bhv = (const float*)d_in[5];
    const float* kvw = (const float*)d_in[6];
    const float* kvb = (const float*)d_in[7];
    const float* blg = (const float*)d_in[8];
    const float* blb = (const float*)d_in[9];
    const float* blm = (const float*)d_in[10];
    const float* blv = (const float*)d_in[11];
    const float* reatt = (const float*)d_in[12];
    float* out = (float*)d_out;

    cudaFuncSetAttribute(kv_kernel,   cudaFuncAttributeMaxDynamicSharedMemorySize, 65536);
    cudaFuncSetAttribute(main_kernel, cudaFuncAttributeMaxDynamicSharedMemorySize, SMEMSZ);

    pool_kernel<<<256, 256>>>(x_h, bhg, bhb, bhm, bhv);
    kv_kernel<<<dim3(8, 8), 256, 65536>>>(kvw, kvb);
    main_kernel<<<152, 512, SMEMSZ>>>(x_l, blg, blb, blm, blv, reatt, out);
}

// round 11
// speedup vs baseline: 1.3086x; 1.3086x over previous
#include <cuda_runtime.h>
#include <cuda_fp16.h>
#include <cstdint>

#define EPSV 1e-5f

// ---- smem map (bytes), tiles XOR-swizzled (chunk16B ^= row&7) ----
#define XL_O   0            // [256 c][64 n] fp16 hi (MMA B + residual), pitch 128B
#define XL_LO  32768        // fp16 lo (residual only)
#define CK_O   65536        // [64 k][256 c] fp16 hi, pitch 512B
#define CK_LO  98304
#define CV_O   131072       // [256 c][64 k] fp16 hi, pitch 128B
#define CV_LO  163840
#define ATT_O  196608       // [64 k][64 n] fp16, pitch 128B (8KB)
#define WMAX_O 204800       // [4][64] f32
#define WSUM_O 205824       // [4][64] f32
#define KB_O   206848       // [64] f32
#define INV_O  207104       // [64] f32
#define SMEMSZ 207360

__device__ float g_p[8 * 128 * 64];
__device__ float g_ck[8 * 64 * 256];   // [b][k][c]
__device__ float g_cv[8 * 256 * 64];   // [b][c][k]

__device__ __forceinline__ uint32_t s2u(const void* p) {
    uint32_t a; asm("{.reg .u64 t; cvta.to.shared.u64 t,%1; cvt.u32.u64 %0,t;}" : "=r"(a) : "l"(p)); return a;
}
__device__ __forceinline__ void ldsm4(uint32_t* r, uint32_t a) {
    asm volatile("ldmatrix.sync.aligned.m8n8.x4.shared.b16 {%0,%1,%2,%3},[%4];"
                 : "=r"(r[0]), "=r"(r[1]), "=r"(r[2]), "=r"(r[3]) : "r"(a));
}
__device__ __forceinline__ void ldsm4t(uint32_t* r, uint32_t a) {
    asm volatile("ldmatrix.sync.aligned.m8n8.x4.trans.shared.b16 {%0,%1,%2,%3},[%4];"
                 : "=r"(r[0]), "=r"(r[1]), "=r"(r[2]), "=r"(r[3]) : "r"(a));
}
__device__ __forceinline__ void hmma(float* d, const uint32_t* a, const uint32_t* b) {
    asm volatile("mma.sync.aligned.m16n8k16.row.col.f32.f16.f16.f32 "
                 "{%0,%1,%2,%3},{%4,%5,%6,%7},{%8,%9},{%0,%1,%2,%3};"
                 : "+f"(d[0]), "+f"(d[1]), "+f"(d[2]), "+f"(d[3])
                 : "r"(a[0]), "r"(a[1]), "r"(a[2]), "r"(a[3]), "r"(b[0]), "r"(b[1]));
}
__device__ __forceinline__ uint32_t hpack(float x, float y) {
    __half2 h = __floats2half2_rn(x, y);
    return *(uint32_t*)&h;
}
__device__ __forceinline__ float2 hunpack(uint32_t u) {
    __half2 h = *(__half2*)&u;
    return __half22float2(h);
}
// split x into fp16 hi + lo
__device__ __forceinline__ void hsplit2(float x, float y, uint32_t& hi, uint32_t& lo) {
    __half hx = __float2half_rn(x), hy = __float2half_rn(y);
    __half lx = __float2half_rn(x - __half2float(hx));
    __half ly = __float2half_rn(y - __half2float(hy));
    __half2 h = __halves2half2(hx, hy), l = __halves2half2(lx, ly);
    hi = *(uint32_t*)&h; lo = *(uint32_t*)&l;
}

// ================= Kernel 1: BN(x_h) + 8x8 maxpool =================
__global__ __launch_bounds__(256) void pool_kernel(
    const float* __restrict__ x_h, const float* __restrict__ gam, const float* __restrict__ bet,
    const float* __restrict__ mu, const float* __restrict__ var)
{
    int idx = blockIdx.x * 256 + threadIdx.x;
    int k = idx & 63, c = (idx >> 6) & 127, b = idx >> 13;
    float scl = gam[c] * rsqrtf(var[c] + EPSV);
    float bia = bet[c] - mu[c] * scl;
    const float* base = x_h + ((((b * 128 + c) * 64) + (k >> 3) * 8) * 64) + (k & 7) * 8;
    float mx = -3.4e38f, mn = 3.4e38f;
#pragma unroll
    for (int r = 0; r < 8; r++) {
        const float4* p4 = (const float4*)(base + r * 64);
        float4 a = p4[0], d = p4[1];
        mx = fmaxf(mx, fmaxf(fmaxf(a.x, a.y), fmaxf(a.z, a.w)));
        mx = fmaxf(mx, fmaxf(fmaxf(d.x, d.y), fmaxf(d.z, d.w)));
        mn = fminf(mn, fminf(fminf(a.x, a.y), fminf(a.z, a.w)));
        mn = fminf(mn, fminf(fminf(d.x, d.y), fminf(d.z, d.w)));
    }
    g_p[idx] = ((scl >= 0.f) ? mx : mn) * scl + bia;
}

// ================= Kernel 2: 1x1 conv -> g_ck [b][k][c] / g_cv [b][c][k] ==========
__global__ __launch_bounds__(256) void kv_kernel(
    const float* __restrict__ kv_w, const float* __restrict__ kv_b)
{
    extern __shared__ float sm2[];
    float* sW = sm2; float* sP = sm2 + 8192;
    int og = blockIdx.x, b = blockIdx.y, t = threadIdx.x;
    const float4* wsrc = (const float4*)(kv_w + og * 64 * 128);
    const float4* psrc = (const float4*)(g_p + b * 8192);
#pragma unroll
    for (int i = 0; i < 8; i++) {
        ((float4*)sW)[t + i * 256] = wsrc[t + i * 256];
        ((float4*)sP)[t + i * 256] = psrc[t + i * 256];
    }
    __syncthreads();
    int ty = t >> 4, tx = t & 15;
    float acc[4][4] = {};
#pragma unroll 4
    for (int c = 0; c < 128; c++) {
        float4 pv = ((const float4*)(sP + c * 64))[tx];
#pragma unroll
        for (int i = 0; i < 4; i++) {
            float w = sW[(ty * 4 + i) * 128 + c];
            acc[i][0] += w * pv.x; acc[i][1] += w * pv.y;
            acc[i][2] += w * pv.z; acc[i][3] += w * pv.w;
        }
    }
#pragma unroll
    for (int i = 0; i < 4; i++) {
        int o = og * 64 + ty * 4 + i;
        float bs = kv_b[o];
#pragma unroll
        for (int j = 0; j < 4; j++) {
            int k = tx * 4 + j;
            float v = acc[i][j] + bs;
            if (o < 256) g_ck[(b * 64 + k) * 256 + o] = v;
            else         g_cv[(b * 256 + (o - 256)) * 64 + k] = v;
        }
    }
}

// ================= Kernel 3: persistent HMMA main (256 thr, 8 warps, fp16) =================
__global__ __launch_bounds__(256) void main_kernel(
    const float* __restrict__ x_l,
    const float* __restrict__ gam, const float* __restrict__ bet,
    const float* __restrict__ mu,  const float* __restrict__ var,
    const float* __restrict__ reatt, float* __restrict__ out)
{
    extern __shared__ __align__(128) char smc[];
    const uint32_t smb = s2u(smc);
    float* WMAX = (float*)(smc + WMAX_O);
    float* WSUM = (float*)(smc + WSUM_O);
    float* KB   = (float*)(smc + KB_O);
    float* INV  = (float*)(smc + INV_O);

    const int t = threadIdx.x, w = t >> 5, lane = t & 31;
    const int g8 = lane >> 2, tid4 = lane & 3;
    const int r8 = lane & 7, i4 = lane >> 3;
    const int bid = blockIdx.x;
    const int start = bid * 13 + (bid < 72 ? bid : 72);
    const int cnt = 13 + (bid < 72 ? 1 : 0);

    const int m0_2 = (w >> 1) * 16;   // phase2: k-row base
    const int n0_2 = (w & 1) * 32;    // phase2: n base
    const int m0_3 = w * 32;          // phase3: c base

    // preload first tile's x_l (16 float4/thread)
    float4 pf[16];
    {
        int b0 = start >> 8, h0 = (start & 255) << 6;
        const float4* xs = (const float4*)(x_l + (long)b0 * 4194304 + h0);
#pragma unroll
        for (int i = 0; i < 16; i++) { int e = t + i * 256; pf[i] = __ldg(&xs[(long)(e >> 4) * 4096 + (e & 15)]); }
    }
    bool pf_valid = true;
    int cur_b = -1;

    for (int g = start; g < start + cnt; ++g) {
        const int b = g >> 8, hw0 = (g & 255) << 6;

        // ---- commit prefetched x_l -> XL hi/lo (swizzled fp16) ----
        if (pf_valid) {
#pragma unroll
            for (int i = 0; i < 16; i++) {
                int e = t + i * 256, c = e >> 4, n4 = e & 15;
                float4 v = pf[i];
                uint32_t h01, l01, h23, l23;
                hsplit2(v.x, v.y, h01, l01);
                hsplit2(v.z, v.w, h23, l23);
                int off = c * 128 + (((n4 >> 1) ^ (c & 7)) << 4) + (n4 & 1) * 8;
                *(uint2*)(smc + XL_O + off)  = make_uint2(h01, h23);
                *(uint2*)(smc + XL_LO + off) = make_uint2(l01, l23);
            }
            pf_valid = false;
        }

        // ---- per-batch restage: ck (BN-scaled, split), cv (split), kb ----
        if (b != cur_b) {
            cur_b = b;
            __syncthreads();
            float* SCL = (float*)(smc + ATT_O);
            float* BIA = (float*)(smc + ATT_O + 1024);
            float sc = gam[t] * rsqrtf(var[t] + EPSV);
            SCL[t] = sc; BIA[t] = bet[t] - mu[t] * sc;
            __syncthreads();
            {   // ck: k = t>>2, 64 c's per thread
                int k = t >> 2, cq = (t & 3) * 64;
                const float* src = g_ck + (b * 64 + k) * 256;
#pragma unroll 4
                for (int cc = 0; cc < 64; cc += 4) {
                    int c = cq + cc;
                    float4 v = *(const float4*)(src + c);
                    v.x *= SCL[c] * 0.125f;   v.y *= SCL[c+1] * 0.125f;
                    v.z *= SCL[c+2] * 0.125f; v.w *= SCL[c+3] * 0.125f;
                    uint32_t h01, l01, h23, l23;
                    hsplit2(v.x, v.y, h01, l01);
                    hsplit2(v.z, v.w, h23, l23);
                    int off = k * 512 + (((c >> 3) ^ (k & 7)) << 4) + (c & 7) * 2;
                    *(uint2*)(smc + CK_O + off)  = make_uint2(h01, h23);
                    *(uint2*)(smc + CK_LO + off) = make_uint2(l01, l23);
                }
            }
            {   // cv: row c = t, 64 k's per thread
                const float* sv = g_cv + (b * 256 + t) * 64;
#pragma unroll 4
                for (int k = 0; k < 64; k += 4) {
                    float4 v = *(const float4*)(sv + k);
                    uint32_t h01, l01, h23, l23;
                    hsplit2(v.x, v.y, h01, l01);
                    hsplit2(v.z, v.w, h23, l23);
                    int off = t * 128 + (((k >> 3) ^ (t & 7)) << 4) + (k & 7) * 2;
                    *(uint2*)(smc + CV_O + off)  = make_uint2(h01, h23);
                    *(uint2*)(smc + CV_LO + off) = make_uint2(l01, l23);
                }
            }
            {   // kb partials
                int kk = t & 63, q = t >> 6;
                const float* bp = g_ck + (b * 64 + kk) * 256 + q * 64;
                float s = 0.f;
#pragma unroll 16
                for (int c = 0; c < 64; c++) s += bp[c] * BIA[q * 64 + c];
                WMAX[q * 64 + kk] = s;
            }
            __syncthreads();
            if (t < 64) KB[t] = 0.125f * (WMAX[t] + WMAX[64 + t] + WMAX[128 + t] + WMAX[192 + t] + __ldg(reatt + t));
        }
        __syncthreads();

        // ================= Phase 2: logits = (ck_hi + ck_lo)^T * xl =================
        float d2[4][4] = {};
        {
            const int arow = m0_2 + r8 + 8 * (i4 & 1);
            const int bro  = r8 + 8 * (i4 & 1);
            const int nch0 = (n0_2 >> 3) + (i4 >> 1);
            uint32_t abh = smb + CK_O + arow * 512;
            uint32_t abl = smb + CK_LO + arow * 512;
            uint32_t bb = smb + XL_O;
#pragma unroll
            for (int s = 0; s < 16; s++) {
                uint32_t ah[4], al[4], b0[4], b1[4];
                int achk = ((s * 2 + (i4 >> 1)) ^ r8) << 4;
                ldsm4(ah, abh + achk);
                ldsm4(al, abl + achk);
                uint32_t br = bb + (s * 16 + bro) * 128;
                ldsm4t(b0, br + ((nch0 ^ r8) << 4));
                ldsm4t(b1, br + (((nch0 + 2) ^ r8) << 4));
                hmma(d2[0], ah, b0); hmma(d2[1], ah, b0 + 2);
                hmma(d2[2], ah, b1); hmma(d2[3], ah, b1 + 2);
                hmma(d2[0], al, b0); hmma(d2[1], al, b0 + 2);
                hmma(d2[2], al, b1); hmma(d2[3], al, b1 + 2);
            }
        }

        // ================= softmax (register-resident) =================
        {
            float kb0 = KB[m0_2 + g8], kb1 = KB[m0_2 + g8 + 8];
            float cm[4][2];
#pragma unroll
            for (int ns = 0; ns < 4; ns++) {
                d2[ns][0] += kb0; d2[ns][1] += kb0;
                d2[ns][2] += kb1; d2[ns][3] += kb1;
                cm[ns][0] = fmaxf(d2[ns][0], d2[ns][2]);
                cm[ns][1] = fmaxf(d2[ns][1], d2[ns][3]);
            }
#pragma unroll
            for (int st = 4; st < 32; st <<= 1)
#pragma unroll
                for (int ns = 0; ns < 4; ns++) {
                    cm[ns][0] = fmaxf(cm[ns][0], __shfl_xor_sync(0xffffffffu, cm[ns][0], st));
                    cm[ns][1] = fmaxf(cm[ns][1], __shfl_xor_sync(0xffffffffu, cm[ns][1], st));
                }
            if (g8 == 0)
#pragma unroll
                for (int ns = 0; ns < 4; ns++) {
                    int n = n0_2 + ns * 8 + tid4 * 2;
                    WMAX[(w >> 1) * 64 + n] = cm[ns][0];
                    WMAX[(w >> 1) * 64 + n + 1] = cm[ns][1];
                }
            __syncthreads();
            if (t < 64) WMAX[t] = fmaxf(fmaxf(WMAX[t], WMAX[64 + t]), fmaxf(WMAX[128 + t], WMAX[192 + t]));
            __syncthreads();

            float sm_[4][2];
            int k0r = m0_2 + g8;
#pragma unroll
            for (int ns = 0; ns < 4; ns++) {
                int n = n0_2 + ns * 8 + tid4 * 2;
                float c0 = WMAX[n], c1 = WMAX[n + 1];
                float e00 = __expf(d2[ns][0] - c0), e01 = __expf(d2[ns][1] - c1);
                float e10 = __expf(d2[ns][2] - c0), e11 = __expf(d2[ns][3] - c1);
                sm_[ns][0] = e00 + e10; sm_[ns][1] = e01 + e11;
                uint32_t h0 = hpack(e00, e01);
                uint32_t h1 = hpack(e10, e11);
                int off0 = k0r * 128 + (((n >> 3)) ^ g8) * 16 + (n & 7) * 2;
                int off1 = off0 + 8 * 128;
                *(uint32_t*)(smc + ATT_O + off0) = h0;
                *(uint32_t*)(smc + ATT_O + off1) = h1;
            }
#pragma unroll
            for (int st = 4; st < 32; st <<= 1)
#pragma unroll
                for (int ns = 0; ns < 4; ns++) {
                    sm_[ns][0] += __shfl_xor_sync(0xffffffffu, sm_[ns][0], st);
                    sm_[ns][1] += __shfl_xor_sync(0xffffffffu, sm_[ns][1], st);
                }
            if (g8 == 0)
#pragma unroll
                for (int ns = 0; ns < 4; ns++) {
                    int n = n0_2 + ns * 8 + tid4 * 2;
                    WSUM[(w >> 1) * 64 + n] = sm_[ns][0];
                    WSUM[(w >> 1) * 64 + n + 1] = sm_[ns][1];
                }
            __syncthreads();
            if (t < 64) INV[t] = 1.f / (WSUM[t] + WSUM[64 + t] + WSUM[128 + t] + WSUM[192 + t]);
            __syncthreads();
        }

        // ================= Phase 3: out-acc = (cv_hi + cv_lo) * att =================
        float d3[2][8][4] = {};
        {
            const int bro = r8 + 8 * (i4 & 1);
            const int aro = r8 + 8 * (i4 & 1);
            uint32_t bb3 = smb + ATT_O;
#pragma unroll
            for (int ks = 0; ks < 4; ks++) {
                uint32_t bfr[4][4];
                uint32_t br = bb3 + (ks * 16 + bro) * 128;
#pragma unroll
                for (int nq = 0; nq < 4; nq++)
                    ldsm4t(bfr[nq], br + (((nq * 2 + (i4 >> 1)) ^ r8) << 4));
                int achk = ((ks * 2 + (i4 >> 1)) ^ r8) << 4;
#pragma unroll
                for (int ms = 0; ms < 2; ms++) {
                    uint32_t ah[4], al[4];
                    uint32_t arow_off = (m0_3 + ms * 16 + aro) * 128 + achk;
                    ldsm4(ah, smb + CV_O + arow_off);
                    ldsm4(al, smb + CV_LO + arow_off);
#pragma unroll
                    for (int nq = 0; nq < 4; nq++) {
                        hmma(d3[ms][nq * 2], ah, bfr[nq]);
                        hmma(d3[ms][nq * 2 + 1], ah, bfr[nq] + 2);
                        hmma(d3[ms][nq * 2], al, bfr[nq]);
                        hmma(d3[ms][nq * 2 + 1], al, bfr[nq] + 2);
                    }
                }
            }
        }

        // ---- prefetch next tile's x_l (hidden under epilogue) ----
        const bool has_next = (g + 1 < start + cnt);
        if (has_next) {
            int gn = g + 1, bn = gn >> 8, hn = (gn & 255) << 6;
            const float4* xs = (const float4*)(x_l + (long)bn * 4194304 + hn);
#pragma unroll
            for (int i = 0; i < 16; i++) { int e = t + i * 256; pf[i] = __ldg(&xs[(long)(e >> 4) * 4096 + (e & 15)]); }
            pf_valid = true;
        }

        // ================= epilogue: residual + 1/sum, direct STG =================
        {
            long gb = (long)b * 4194304 + hw0;
#pragma unroll
            for (int ms = 0; ms < 2; ms++) {
                int c0r = m0_3 + ms * 16 + g8, c1r = c0r + 8;
#pragma unroll
                for (int nq2 = 0; nq2 < 8; nq2++) {
                    int n = nq2 * 8 + tid4 * 2;
                    float2 iv = *(float2*)(INV + n);
                    int sw = ((n >> 3) ^ g8) << 4;
                    int o0 = c0r * 128 + sw + (n & 7) * 2;
                    int o1 = c1r * 128 + sw + (n & 7) * 2;
                    float2 h0 = hunpack(*(uint32_t*)(smc + XL_O + o0));
                    float2 l0 = hunpack(*(uint32_t*)(smc + XL_LO + o0));
                    float2 h1 = hunpack(*(uint32_t*)(smc + XL_O + o1));
                    float2 l1 = hunpack(*(uint32_t*)(smc + XL_LO + o1));
                    float2 r0, r1;
                    r0.x = h0.x + l0.x + d3[ms][nq2][0] * iv.x;
                    r0.y = h0.y + l0.y + d3[ms][nq2][1] * iv.y;
                    r1.x = h1.x + l1.x + d3[ms][nq2][2] * iv.x;
                    r1.y = h1.y + l1.y + d3[ms][nq2][3] * iv.y;
                    *(float2*)(out + gb + (long)c0r * 16384 + n) = r0;
                    *(float2*)(out + gb + (long)c1r * 16384 + n) = r1;
                }
            }
        }
        __syncthreads();
    }
}

// ============================================================
extern "C" void kernel_launch(void* const* d_in, const int* in_sizes, int n_in,
                              void* d_out, int out_size)
{
    const float* x_h = (const float*)d_in[0];
    const float* x_l = (const float*)d_in[1];
    const float* bhg = (const float*)d_in[2];
    const float* bhb = (const float*)d_in[3];
    const float* bhm = (const float*)d_in[4];
    const float* bhv = (const float*)d_in[5];
    const float* kvw = (const float*)d_in[6];
    const float* kvb = (const float*)d_in[7];
    const float* blg = (const float*)d_in[8];
    const float* blb = (const float*)d_in[9];
    const float* blm = (const float*)d_in[10];
    const float* blv = (const float*)d_in[11];
    const float* reatt = (const float*)d_in[12];
    float* out = (float*)d_out;

    cudaFuncSetAttribute(kv_kernel,   cudaFuncAttributeMaxDynamicSharedMemorySize, 65536);
    cudaFuncSetAttribute(main_kernel, cudaFuncAttributeMaxDynamicSharedMemorySize, SMEMSZ);

    pool_kernel<<<256, 256>>>(x_h, bhg, bhb, bhm, bhv);
    kv_kernel<<<dim3(8, 8), 256, 65536>>>(kvw, kvb);
    main_kernel<<<152, 256, SMEMSZ>>>(x_l, blg, blb, blm, blv, reatt, out);
}

// round 12
// speedup vs baseline: 1.3705x; 1.0473x over previous
#include <cuda_runtime.h>
#include <cuda_fp16.h>
#include <cstdint>

#define EPSV 1e-5f

// ---- smem map (bytes), tiles XOR-swizzled (chunk16B ^= row&7) ----
#define XLH0   0            // [2 buf][256 c][64 n] fp16 hi, pitch 128B
#define XLL0   65536        // [2 buf] fp16 lo (residual only)
#define CK_O   131072       // [64 k][256 c] fp16, pitch 512B
#define CV_O   163840       // [256 c][64 k] fp16, pitch 128B
#define ATT_O  196608       // [64 k][64 n] fp16, pitch 128B (8KB)
#define WMAX_O 204800       // [4][64] f32
#define WSUM_O 205824       // [4][64] f32
#define KB_O   206848       // [64] f32
#define INV_O  207104       // [64] f32
#define SMEMSZ 207360

__device__ float g_p[8 * 128 * 64];
__device__ float g_ck[8 * 64 * 256];   // [b][k][c]
__device__ float g_cv[8 * 256 * 64];   // [b][c][k]

__device__ __forceinline__ uint32_t s2u(const void* p) {
    uint32_t a; asm("{.reg .u64 t; cvta.to.shared.u64 t,%1; cvt.u32.u64 %0,t;}" : "=r"(a) : "l"(p)); return a;
}
__device__ __forceinline__ void ldsm4(uint32_t* r, uint32_t a) {
    asm volatile("ldmatrix.sync.aligned.m8n8.x4.shared.b16 {%0,%1,%2,%3},[%4];"
                 : "=r"(r[0]), "=r"(r[1]), "=r"(r[2]), "=r"(r[3]) : "r"(a));
}
__device__ __forceinline__ void ldsm4t(uint32_t* r, uint32_t a) {
    asm volatile("ldmatrix.sync.aligned.m8n8.x4.trans.shared.b16 {%0,%1,%2,%3},[%4];"
                 : "=r"(r[0]), "=r"(r[1]), "=r"(r[2]), "=r"(r[3]) : "r"(a));
}
__device__ __forceinline__ void hmma(float* d, const uint32_t* a, const uint32_t* b) {
    asm volatile("mma.sync.aligned.m16n8k16.row.col.f32.f16.f16.f32 "
                 "{%0,%1,%2,%3},{%4,%5,%6,%7},{%8,%9},{%0,%1,%2,%3};"
                 : "+f"(d[0]), "+f"(d[1]), "+f"(d[2]), "+f"(d[3])
                 : "r"(a[0]), "r"(a[1]), "r"(a[2]), "r"(a[3]), "r"(b[0]), "r"(b[1]));
}
__device__ __forceinline__ uint32_t hpack(float x, float y) {
    __half2 h = __floats2half2_rn(x, y);
    return *(uint32_t*)&h;
}
__device__ __forceinline__ float2 hunpack(uint32_t u) {
    __half2 h = *(__half2*)&u;
    return __half22float2(h);
}
__device__ __forceinline__ void hsplit2(float x, float y, uint32_t& hi, uint32_t& lo) {
    __half hx = __float2half_rn(x), hy = __float2half_rn(y);
    __half lx = __float2half_rn(x - __half2float(hx));
    __half ly = __float2half_rn(y - __half2float(hy));
    __half2 h = __halves2half2(hx, hy), l = __halves2half2(lx, ly);
    hi = *(uint32_t*)&h; lo = *(uint32_t*)&l;
}

// ================= Kernel 1: BN(x_h) + 8x8 maxpool (2 thr/window) =================
__global__ __launch_bounds__(256) void pool_kernel(
    const float* __restrict__ x_h, const float* __restrict__ gam, const float* __restrict__ bet,
    const float* __restrict__ mu, const float* __restrict__ var)
{
    int idx = blockIdx.x * 256 + threadIdx.x;       // 131072
    int half = idx & 1;
    int w0 = idx >> 1;                              // window id, 65536
    int k = w0 & 63, c = (w0 >> 6) & 127, b = w0 >> 13;
    float scl = gam[c] * rsqrtf(var[c] + EPSV);
    float bia = bet[c] - mu[c] * scl;
    const float* base = x_h + ((((b * 128 + c) * 64) + (k >> 3) * 8 + half * 4) * 64) + (k & 7) * 8;
    float mx = -3.4e38f, mn = 3.4e38f;
#pragma unroll
    for (int r = 0; r < 4; r++) {
        const float4* p4 = (const float4*)(base + r * 64);
        float4 a = p4[0], d = p4[1];
        mx = fmaxf(mx, fmaxf(fmaxf(a.x, a.y), fmaxf(a.z, a.w)));
        mx = fmaxf(mx, fmaxf(fmaxf(d.x, d.y), fmaxf(d.z, d.w)));
        mn = fminf(mn, fminf(fminf(a.x, a.y), fminf(a.z, a.w)));
        mn = fminf(mn, fminf(fminf(d.x, d.y), fminf(d.z, d.w)));
    }
    mx = fmaxf(mx, __shfl_xor_sync(0xffffffffu, mx, 1));
    mn = fminf(mn, __shfl_xor_sync(0xffffffffu, mn, 1));
    if (!half) g_p[w0] = ((scl >= 0.f) ? mx : mn) * scl + bia;
}

// ================= Kernel 2: 1x1 conv -> g_ck [b][k][c] / g_cv [b][c][k] ==========
__global__ __launch_bounds__(256) void kv_kernel(
    const float* __restrict__ kv_w, const float* __restrict__ kv_b)
{
    extern __shared__ float sm2[];
    float* sW = sm2; float* sP = sm2 + 8192;
    int og = blockIdx.x, b = blockIdx.y, t = threadIdx.x;
    const float4* wsrc = (const float4*)(kv_w + og * 64 * 128);
    const float4* psrc = (const float4*)(g_p + b * 8192);
#pragma unroll
    for (int i = 0; i < 8; i++) {
        ((float4*)sW)[t + i * 256] = wsrc[t + i * 256];
        ((float4*)sP)[t + i * 256] = psrc[t + i * 256];
    }
    __syncthreads();
    int ty = t >> 4, tx = t & 15;
    float acc[4][4] = {};
#pragma unroll 4
    for (int c = 0; c < 128; c++) {
        float4 pv = ((const float4*)(sP + c * 64))[tx];
#pragma unroll
        for (int i = 0; i < 4; i++) {
            float w = sW[(ty * 4 + i) * 128 + c];
            acc[i][0] += w * pv.x; acc[i][1] += w * pv.y;
            acc[i][2] += w * pv.z; acc[i][3] += w * pv.w;
        }
    }
#pragma unroll
    for (int i = 0; i < 4; i++) {
        int o = og * 64 + ty * 4 + i;
        float bs = kv_b[o];
#pragma unroll
        for (int j = 0; j < 4; j++) {
            int k = tx * 4 + j;
            float v = acc[i][j] + bs;
            if (o < 256) g_ck[(b * 64 + k) * 256 + o] = v;
            else         g_cv[(b * 256 + (o - 256)) * 64 + k] = v;
        }
    }
}

// ================= Kernel 3: persistent HMMA main (256 thr, 8 warps, fp16) =================
__global__ __launch_bounds__(256) void main_kernel(
    const float* __restrict__ x_l,
    const float* __restrict__ gam, const float* __restrict__ bet,
    const float* __restrict__ mu,  const float* __restrict__ var,
    const float* __restrict__ reatt, float* __restrict__ out)
{
    extern __shared__ __align__(128) char smc[];
    const uint32_t smb = s2u(smc);
    float* WMAX = (float*)(smc + WMAX_O);
    float* WSUM = (float*)(smc + WSUM_O);
    float* KB   = (float*)(smc + KB_O);
    float* INV  = (float*)(smc + INV_O);

    const int t = threadIdx.x, w = t >> 5, lane = t & 31;
    const int g8 = lane >> 2, tid4 = lane & 3;
    const int r8 = lane & 7, i4 = lane >> 3;
    const int bid = blockIdx.x;
    const int start = bid * 13 + (bid < 72 ? bid : 72);
    const int cnt = 13 + (bid < 72 ? 1 : 0);

    const int m0_2 = (w >> 1) * 16;   // phase2: k-row base
    const int n0_2 = (w & 1) * 32;    // phase2: n base
    const int m0_3 = w * 32;          // phase3: c base

    // preload first tile's x_l
    float4 pf[16];
    {
        int b0 = start >> 8, h0 = (start & 255) << 6;
        const float4* xs = (const float4*)(x_l + (long)b0 * 4194304 + h0);
#pragma unroll
        for (int i = 0; i < 16; i++) { int e = t + i * 256; pf[i] = __ldg(&xs[(long)(e >> 4) * 4096 + (e & 15)]); }
    }
    // commit first tile into buffer 0
    int buf = 0;
    {
#pragma unroll
        for (int i = 0; i < 16; i++) {
            int e = t + i * 256, c = e >> 4, n4 = e & 15;
            float4 v = pf[i];
            uint32_t h01, l01, h23, l23;
            hsplit2(v.x, v.y, h01, l01);
            hsplit2(v.z, v.w, h23, l23);
            int off = c * 128 + (((n4 >> 1) ^ (c & 7)) << 4) + (n4 & 1) * 8;
            *(uint2*)(smc + XLH0 + off)  = make_uint2(h01, h23);
            *(uint2*)(smc + XLL0 + off) = make_uint2(l01, l23);
        }
    }
    int cur_b = -1;

    for (int g = start; g < start + cnt; ++g) {
        const int b = g >> 8, hw0 = (g & 255) << 6;

        // ---- per-batch restage: ck (BN-scaled, fp16), cv (fp16), kb ----
        if (b != cur_b) {
            cur_b = b;
            __syncthreads();
            float* SCL = (float*)(smc + ATT_O);
            float* BIA = (float*)(smc + ATT_O + 1024);
            float sc = gam[t] * rsqrtf(var[t] + EPSV);
            SCL[t] = sc; BIA[t] = bet[t] - mu[t] * sc;
            __syncthreads();
            {   // ck: k = t>>2, 64 c's per thread
                int k = t >> 2, cq = (t & 3) * 64;
                const float* src = g_ck + (b * 64 + k) * 256;
#pragma unroll 4
                for (int cc = 0; cc < 64; cc += 4) {
                    int c = cq + cc;
                    float4 v = *(const float4*)(src + c);
                    v.x *= SCL[c] * 0.125f;   v.y *= SCL[c+1] * 0.125f;
                    v.z *= SCL[c+2] * 0.125f; v.w *= SCL[c+3] * 0.125f;
                    int off = k * 512 + (((c >> 3) ^ (k & 7)) << 4) + (c & 7) * 2;
                    *(uint2*)(smc + CK_O + off) = make_uint2(hpack(v.x, v.y), hpack(v.z, v.w));
                }
            }
            {   // cv: row c = t, 64 k's per thread
                const float* sv = g_cv + (b * 256 + t) * 64;
#pragma unroll 4
                for (int k = 0; k < 64; k += 4) {
                    float4 v = *(const float4*)(sv + k);
                    int off = t * 128 + (((k >> 3) ^ (t & 7)) << 4) + (k & 7) * 2;
                    *(uint2*)(smc + CV_O + off) = make_uint2(hpack(v.x, v.y), hpack(v.z, v.w));
                }
            }
            {   // kb partials
                int kk = t & 63, q = t >> 6;
                const float* bp = g_ck + (b * 64 + kk) * 256 + q * 64;
                float s = 0.f;
#pragma unroll 16
                for (int c = 0; c < 64; c++) s += bp[c] * BIA[q * 64 + c];
                WMAX[q * 64 + kk] = s;
            }
            __syncthreads();
            if (t < 64) KB[t] = 0.125f * (WMAX[t] + WMAX[64 + t] + WMAX[128 + t] + WMAX[192 + t] + __ldg(reatt + t));
        }
        __syncthreads();

        const uint32_t xlh = smb + XLH0 + buf * 32768;

        // ================= Phase 2: logits = ck^T * xl_hi =================
        float d2[4][4] = {};
        {
            const int arow = m0_2 + r8 + 8 * (i4 & 1);
            const int bro  = r8 + 8 * (i4 & 1);
            const int nch0 = (n0_2 >> 3) + (i4 >> 1);
            uint32_t ab = smb + CK_O + arow * 512;
#pragma unroll
            for (int s = 0; s < 16; s++) {
                uint32_t a[4], b0[4], b1[4];
                ldsm4(a, ab + (((s * 2 + (i4 >> 1)) ^ r8) << 4));
                uint32_t br = xlh + (s * 16 + bro) * 128;
                ldsm4t(b0, br + ((nch0 ^ r8) << 4));
                ldsm4t(b1, br + (((nch0 + 2) ^ r8) << 4));
                hmma(d2[0], a, b0); hmma(d2[1], a, b0 + 2);
                hmma(d2[2], a, b1); hmma(d2[3], a, b1 + 2);
            }
        }

        // ================= softmax (register-resident) =================
        {
            float kb0 = KB[m0_2 + g8], kb1 = KB[m0_2 + g8 + 8];
            float cm[4][2];
#pragma unroll
            for (int ns = 0; ns < 4; ns++) {
                d2[ns][0] += kb0; d2[ns][1] += kb0;
                d2[ns][2] += kb1; d2[ns][3] += kb1;
                cm[ns][0] = fmaxf(d2[ns][0], d2[ns][2]);
                cm[ns][1] = fmaxf(d2[ns][1], d2[ns][3]);
            }
#pragma unroll
            for (int st = 4; st < 32; st <<= 1)
#pragma unroll
                for (int ns = 0; ns < 4; ns++) {
                    cm[ns][0] = fmaxf(cm[ns][0], __shfl_xor_sync(0xffffffffu, cm[ns][0], st));
                    cm[ns][1] = fmaxf(cm[ns][1], __shfl_xor_sync(0xffffffffu, cm[ns][1], st));
                }
            if (g8 == 0)
#pragma unroll
                for (int ns = 0; ns < 4; ns++) {
                    int n = n0_2 + ns * 8 + tid4 * 2;
                    WMAX[(w >> 1) * 64 + n] = cm[ns][0];
                    WMAX[(w >> 1) * 64 + n + 1] = cm[ns][1];
                }
            __syncthreads();
            if (t < 64) WMAX[t] = fmaxf(fmaxf(WMAX[t], WMAX[64 + t]), fmaxf(WMAX[128 + t], WMAX[192 + t]));
            __syncthreads();

            float sm_[4][2];
            int k0r = m0_2 + g8;
#pragma unroll
            for (int ns = 0; ns < 4; ns++) {
                int n = n0_2 + ns * 8 + tid4 * 2;
                float c0 = WMAX[n], c1 = WMAX[n + 1];
                float e00 = __expf(d2[ns][0] - c0), e01 = __expf(d2[ns][1] - c1);
                float e10 = __expf(d2[ns][2] - c0), e11 = __expf(d2[ns][3] - c1);
                sm_[ns][0] = e00 + e10; sm_[ns][1] = e01 + e11;
                int off0 = k0r * 128 + (((n >> 3)) ^ g8) * 16 + (n & 7) * 2;
                int off1 = off0 + 8 * 128;
                *(uint32_t*)(smc + ATT_O + off0) = hpack(e00, e01);
                *(uint32_t*)(smc + ATT_O + off1) = hpack(e10, e11);
            }
#pragma unroll
            for (int st = 4; st < 32; st <<= 1)
#pragma unroll
                for (int ns = 0; ns < 4; ns++) {
                    sm_[ns][0] += __shfl_xor_sync(0xffffffffu, sm_[ns][0], st);
                    sm_[ns][1] += __shfl_xor_sync(0xffffffffu, sm_[ns][1], st);
                }
            if (g8 == 0)
#pragma unroll
                for (int ns = 0; ns < 4; ns++) {
                    int n = n0_2 + ns * 8 + tid4 * 2;
                    WSUM[(w >> 1) * 64 + n] = sm_[ns][0];
                    WSUM[(w >> 1) * 64 + n + 1] = sm_[ns][1];
                }
            __syncthreads();
            if (t < 64) INV[t] = 1.f / (WSUM[t] + WSUM[64 + t] + WSUM[128 + t] + WSUM[192 + t]);
            __syncthreads();
        }

        // ================= Phase 3: out-acc = cv * att =================
        float d3[2][8][4] = {};
        {
            const int bro = r8 + 8 * (i4 & 1);
            const int aro = r8 + 8 * (i4 & 1);
            uint32_t bb3 = smb + ATT_O;
#pragma unroll
            for (int ks = 0; ks < 4; ks++) {
                uint32_t bfr[4][4];
                uint32_t br = bb3 + (ks * 16 + bro) * 128;
#pragma unroll
                for (int nq = 0; nq < 4; nq++)
                    ldsm4t(bfr[nq], br + (((nq * 2 + (i4 >> 1)) ^ r8) << 4));
                int achk = ((ks * 2 + (i4 >> 1)) ^ r8) << 4;
#pragma unroll
                for (int ms = 0; ms < 2; ms++) {
                    uint32_t a[4];
                    ldsm4(a, smb + CV_O + (m0_3 + ms * 16 + aro) * 128 + achk);
#pragma unroll
                    for (int nq = 0; nq < 4; nq++) {
                        hmma(d3[ms][nq * 2], a, bfr[nq]);
                        hmma(d3[ms][nq * 2 + 1], a, bfr[nq] + 2);
                    }
                }
            }
        }

        // ---- prefetch next tile's x_l (hidden under epilogue) ----
        const bool has_next = (g + 1 < start + cnt);
        if (has_next) {
            int gn = g + 1, bn = gn >> 8, hn = (gn & 255) << 6;
            const float4* xs = (const float4*)(x_l + (long)bn * 4194304 + hn);
#pragma unroll
            for (int i = 0; i < 16; i++) { int e = t + i * 256; pf[i] = __ldg(&xs[(long)(e >> 4) * 4096 + (e & 15)]); }
        }

        // ================= epilogue: residual + 1/sum, direct STG =================
        {
            const uint32_t xll = smb + XLL0 + buf * 32768;
            long gb = (long)b * 4194304 + hw0;
#pragma unroll
            for (int ms = 0; ms < 2; ms++) {
                int c0r = m0_3 + ms * 16 + g8, c1r = c0r + 8;
#pragma unroll
                for (int nq2 = 0; nq2 < 8; nq2++) {
                    int n = nq2 * 8 + tid4 * 2;
                    float2 iv = *(float2*)(INV + n);
                    int sw = ((n >> 3) ^ g8) << 4;
                    int o0 = c0r * 128 + sw + (n & 7) * 2;
                    int o1 = c1r * 128 + sw + (n & 7) * 2;
                    float2 h0 = hunpack(*(uint32_t*)(xlh + o0 - smb + (size_t)smc));
                    float2 l0 = hunpack(*(uint32_t*)(xll + o0 - smb + (size_t)smc));
                    float2 h1 = hunpack(*(uint32_t*)(xlh + o1 - smb + (size_t)smc));
                    float2 l1 = hunpack(*(uint32_t*)(xll + o1 - smb + (size_t)smc));
                    float2 r0, r1;
                    r0.x = h0.x + l0.x + d3[ms][nq2][0] * iv.x;
                    r0.y = h0.y + l0.y + d3[ms][nq2][1] * iv.y;
                    r1.x = h1.x + l1.x + d3[ms][nq2][2] * iv.x;
                    r1.y = h1.y + l1.y + d3[ms][nq2][3] * iv.y;
                    *(float2*)(out + gb + (long)c0r * 16384 + n) = r0;
                    *(float2*)(out + gb + (long)c1r * 16384 + n) = r1;
                }
            }
        }

        // ---- commit prefetched tile into the OTHER buffer (overlaps epilogue tail) ----
        if (has_next) {
            int nb = buf ^ 1;
#pragma unroll
            for (int i = 0; i < 16; i++) {
                int e = t + i * 256, c = e >> 4, n4 = e & 15;
                float4 v = pf[i];
                uint32_t h01, l01, h23, l23;
                hsplit2(v.x, v.y, h01, l01);
                hsplit2(v.z, v.w, h23, l23);
                int off = nb * 32768 + c * 128 + (((n4 >> 1) ^ (c & 7)) << 4) + (n4 & 1) * 8;
                *(uint2*)(smc + XLH0 + off) = make_uint2(h01, h23);
                *(uint2*)(smc + XLL0 + off) = make_uint2(l01, l23);
            }
        }
        __syncthreads();
        buf ^= 1;
    }
}

// ============================================================
extern "C" void kernel_launch(void* const* d_in, const int* in_sizes, int n_in,
                              void* d_out, int out_size)
{
    const float* x_h = (const float*)d_in[0];
    const float* x_l = (const float*)d_in[1];
    const float* bhg = (const float*)d_in[2];
    const float* bhb = (const float*)d_in[3];
    const float* bhm = (const float*)d_in[4];
    const float* bhv = (const float*)d_in[5];
    const float* kvw = (const float*)d_in[6];
    const float* kvb = (const float*)d_in[7];
    const float* blg = (const float*)d_in[8];
    const float* blb = (const float*)d_in[9];
    const float* blm = (const float*)d_in[10];
    const float* blv = (const float*)d_in[11];
    const float* reatt = (const float*)d_in[12];
    float* out = (float*)d_out;

    cudaFuncSetAttribute(kv_kernel,   cudaFuncAttributeMaxDynamicSharedMemorySize, 65536);
    cudaFuncSetAttribute(main_kernel, cudaFuncAttributeMaxDynamicSharedMemorySize, SMEMSZ);

    pool_kernel<<<512, 256>>>(x_h, bhg, bhb, bhm, bhv);
    kv_kernel<<<dim3(8, 8), 256, 65536>>>(kvw, kvb);
    main_kernel<<<152, 256, SMEMSZ>>>(x_l, blg, blb, blm, blv, reatt, out);
}

// round 13
// speedup vs baseline: 1.4988x; 1.0936x over previous
#include <cuda_runtime.h>
#include <cuda_fp16.h>
#include <cstdint>

#define EPSV 1e-5f

// ---- smem map (bytes), tiles XOR-swizzled (chunk16B ^= row&7) ----
#define XLH0   0            // [2 buf][256 c][64 n] fp16 hi, pitch 128B
#define XLL0   65536        // [2 buf] fp16 lo (residual only)
#define CK_O   131072       // [64 k][256 c] fp16, pitch 512B
#define CV_O   163840       // [256 c][64 k] fp16, pitch 128B
#define ATT_O  196608       // [64 k][64 n] fp16, pitch 128B (8KB)
#define WMAX_O 204800       // [4][64] f32
#define WSUM_O 205824       // [4][64] f32
#define KB_O   206848       // [64] f32
#define INV_O  207104       // [64] f32
#define SMEMSZ 207360

__device__ float g_p[8 * 128 * 64];
__device__ float g_ck[8 * 64 * 256];   // [b][k][c]
__device__ float g_cv[8 * 256 * 64];   // [b][c][k]

__device__ __forceinline__ uint32_t s2u(const void* p) {
    uint32_t a; asm("{.reg .u64 t; cvta.to.shared.u64 t,%1; cvt.u32.u64 %0,t;}" : "=r"(a) : "l"(p)); return a;
}
__device__ __forceinline__ void ldsm4(uint32_t* r, uint32_t a) {
    asm volatile("ldmatrix.sync.aligned.m8n8.x4.shared.b16 {%0,%1,%2,%3},[%4];"
                 : "=r"(r[0]), "=r"(r[1]), "=r"(r[2]), "=r"(r[3]) : "r"(a));
}
__device__ __forceinline__ void ldsm4t(uint32_t* r, uint32_t a) {
    asm volatile("ldmatrix.sync.aligned.m8n8.x4.trans.shared.b16 {%0,%1,%2,%3},[%4];"
                 : "=r"(r[0]), "=r"(r[1]), "=r"(r[2]), "=r"(r[3]) : "r"(a));
}
__device__ __forceinline__ void hmma(float* d, const uint32_t* a, const uint32_t* b) {
    asm volatile("mma.sync.aligned.m16n8k16.row.col.f32.f16.f16.f32 "
                 "{%0,%1,%2,%3},{%4,%5,%6,%7},{%8,%9},{%0,%1,%2,%3};"
                 : "+f"(d[0]), "+f"(d[1]), "+f"(d[2]), "+f"(d[3])
                 : "r"(a[0]), "r"(a[1]), "r"(a[2]), "r"(a[3]), "r"(b[0]), "r"(b[1]));
}
__device__ __forceinline__ uint32_t hpack(float x, float y) {
    __half2 h = __floats2half2_rn(x, y);
    return *(uint32_t*)&h;
}
__device__ __forceinline__ float2 hunpack(uint32_t u) {
    __half2 h = *(__half2*)&u;
    return __half22float2(h);
}
__device__ __forceinline__ void hsplit2(float x, float y, uint32_t& hi, uint32_t& lo) {
    __half hx = __float2half_rn(x), hy = __float2half_rn(y);
    __half lx = __float2half_rn(x - __half2float(hx));
    __half ly = __float2half_rn(y - __half2float(hy));
    __half2 h = __halves2half2(hx, hy), l = __halves2half2(lx, ly);
    hi = *(uint32_t*)&h; lo = *(uint32_t*)&l;
}

// ================= Kernel 1: BN(x_h) + 8x8 maxpool (4 thr/window) =================
__global__ __launch_bounds__(256) void pool_kernel(
    const float* __restrict__ x_h, const float* __restrict__ gam, const float* __restrict__ bet,
    const float* __restrict__ mu, const float* __restrict__ var)
{
    int idx = blockIdx.x * 256 + threadIdx.x;       // 262144
    int q = idx & 3;
    int w0 = idx >> 2;                              // window id, 65536
    int k = w0 & 63, c = (w0 >> 6) & 127, b = w0 >> 13;
    float scl = gam[c] * rsqrtf(var[c] + EPSV);
    float bia = bet[c] - mu[c] * scl;
    const float* base = x_h + ((((b * 128 + c) * 64) + (k >> 3) * 8 + q * 2) * 64) + (k & 7) * 8;
    float mx = -3.4e38f, mn = 3.4e38f;
#pragma unroll
    for (int r = 0; r < 2; r++) {
        const float4* p4 = (const float4*)(base + r * 64);
        float4 a = p4[0], d = p4[1];
        mx = fmaxf(mx, fmaxf(fmaxf(a.x, a.y), fmaxf(a.z, a.w)));
        mx = fmaxf(mx, fmaxf(fmaxf(d.x, d.y), fmaxf(d.z, d.w)));
        mn = fminf(mn, fminf(fminf(a.x, a.y), fminf(a.z, a.w)));
        mn = fminf(mn, fminf(fminf(d.x, d.y), fminf(d.z, d.w)));
    }
    mx = fmaxf(mx, __shfl_xor_sync(0xffffffffu, mx, 1));
    mn = fminf(mn, __shfl_xor_sync(0xffffffffu, mn, 1));
    mx = fmaxf(mx, __shfl_xor_sync(0xffffffffu, mx, 2));
    mn = fminf(mn, __shfl_xor_sync(0xffffffffu, mn, 2));
    if (!q) g_p[w0] = ((scl >= 0.f) ? mx : mn) * scl + bia;
}

// ================= Kernel 2: 1x1 conv -> g_ck [b][k][c] / g_cv [b][c][k] ==========
__global__ __launch_bounds__(256) void kv_kernel(
    const float* __restrict__ kv_w, const float* __restrict__ kv_b)
{
    extern __shared__ float sm2[];
    float* sW = sm2; float* sP = sm2 + 8192;
    int og = blockIdx.x, b = blockIdx.y, t = threadIdx.x;
    const float4* wsrc = (const float4*)(kv_w + og * 64 * 128);
    const float4* psrc = (const float4*)(g_p + b * 8192);
#pragma unroll
    for (int i = 0; i < 8; i++) {
        ((float4*)sW)[t + i * 256] = wsrc[t + i * 256];
        ((float4*)sP)[t + i * 256] = psrc[t + i * 256];
    }
    __syncthreads();
    int ty = t >> 4, tx = t & 15;
    float acc[4][4] = {};
#pragma unroll 4
    for (int c = 0; c < 128; c++) {
        float4 pv = ((const float4*)(sP + c * 64))[tx];
#pragma unroll
        for (int i = 0; i < 4; i++) {
            float w = sW[(ty * 4 + i) * 128 + c];
            acc[i][0] += w * pv.x; acc[i][1] += w * pv.y;
            acc[i][2] += w * pv.z; acc[i][3] += w * pv.w;
        }
    }
#pragma unroll
    for (int i = 0; i < 4; i++) {
        int o = og * 64 + ty * 4 + i;
        float bs = kv_b[o];
#pragma unroll
        for (int j = 0; j < 4; j++) {
            int k = tx * 4 + j;
            float v = acc[i][j] + bs;
            if (o < 256) g_ck[(b * 64 + k) * 256 + o] = v;
            else         g_cv[(b * 256 + (o - 256)) * 64 + k] = v;
        }
    }
}

// ================= Kernel 3: persistent HMMA main (256 thr, 8 warps, fp16) =================
__global__ __launch_bounds__(256) void main_kernel(
    const float* __restrict__ x_l,
    const float* __restrict__ gam, const float* __restrict__ bet,
    const float* __restrict__ mu,  const float* __restrict__ var,
    const float* __restrict__ reatt, float* __restrict__ out)
{
    extern __shared__ __align__(128) char smc[];
    const uint32_t smb = s2u(smc);
    float* WMAX = (float*)(smc + WMAX_O);
    float* WSUM = (float*)(smc + WSUM_O);
    float* KB   = (float*)(smc + KB_O);
    float* INV  = (float*)(smc + INV_O);

    const int t = threadIdx.x, w = t >> 5, lane = t & 31;
    const int g8 = lane >> 2, tid4 = lane & 3;
    const int r8 = lane & 7, i4 = lane >> 3;
    const int bid = blockIdx.x;
    const int start = bid * 13 + (bid < 72 ? bid : 72);
    const int cnt = 13 + (bid < 72 ? 1 : 0);

    const int m0_2 = (w >> 1) * 16;   // phase2: k-row base
    const int n0_2 = (w & 1) * 32;    // phase2: n base
    const int m0_3 = w * 32;          // phase3: c base

    // preload + commit first tile into buffer 0
    float4 pf[16];
    {
        int b0 = start >> 8, h0 = (start & 255) << 6;
        const float4* xs = (const float4*)(x_l + (long)b0 * 4194304 + h0);
#pragma unroll
        for (int i = 0; i < 16; i++) { int e = t + i * 256; pf[i] = __ldg(&xs[(long)(e >> 4) * 4096 + (e & 15)]); }
    }
    int buf = 0;
    {
#pragma unroll
        for (int i = 0; i < 16; i++) {
            int e = t + i * 256, c = e >> 4, n4 = e & 15;
            float4 v = pf[i];
            uint32_t h01, l01, h23, l23;
            hsplit2(v.x, v.y, h01, l01);
            hsplit2(v.z, v.w, h23, l23);
            int off = c * 128 + (((n4 >> 1) ^ (c & 7)) << 4) + (n4 & 1) * 8;
            *(uint2*)(smc + XLH0 + off)  = make_uint2(h01, h23);
            *(uint2*)(smc + XLL0 + off) = make_uint2(l01, l23);
        }
    }
    int cur_b = -1;

    for (int g = start; g < start + cnt; ++g) {
        const int b = g >> 8, hw0 = (g & 255) << 6;

        // ---- per-batch restage: ck (BN-scaled, fp16), cv (fp16), kb ----
        if (b != cur_b) {
            cur_b = b;
            __syncthreads();
            float* SCL = (float*)(smc + ATT_O);
            float* BIA = (float*)(smc + ATT_O + 1024);
            float sc = gam[t] * rsqrtf(var[t] + EPSV);
            SCL[t] = sc; BIA[t] = bet[t] - mu[t] * sc;
            __syncthreads();
            {   // ck: k = t>>2, 64 c's per thread
                int k = t >> 2, cq = (t & 3) * 64;
                const float* src = g_ck + (b * 64 + k) * 256;
#pragma unroll 4
                for (int cc = 0; cc < 64; cc += 4) {
                    int c = cq + cc;
                    float4 v = *(const float4*)(src + c);
                    v.x *= SCL[c] * 0.125f;   v.y *= SCL[c+1] * 0.125f;
                    v.z *= SCL[c+2] * 0.125f; v.w *= SCL[c+3] * 0.125f;
                    int off = k * 512 + (((c >> 3) ^ (k & 7)) << 4) + (c & 7) * 2;
                    *(uint2*)(smc + CK_O + off) = make_uint2(hpack(v.x, v.y), hpack(v.z, v.w));
                }
            }
            {   // cv: row c = t, 64 k's per thread
                const float* sv = g_cv + (b * 256 + t) * 64;
#pragma unroll 4
                for (int k = 0; k < 64; k += 4) {
                    float4 v = *(const float4*)(sv + k);
                    int off = t * 128 + (((k >> 3) ^ (t & 7)) << 4) + (k & 7) * 2;
                    *(uint2*)(smc + CV_O + off) = make_uint2(hpack(v.x, v.y), hpack(v.z, v.w));
                }
            }
            {   // kb partials
                int kk = t & 63, q = t >> 6;
                const float* bp = g_ck + (b * 64 + kk) * 256 + q * 64;
                float s = 0.f;
#pragma unroll 16
                for (int c = 0; c < 64; c++) s += bp[c] * BIA[q * 64 + c];
                WMAX[q * 64 + kk] = s;
            }
            __syncthreads();
            if (t < 64) KB[t] = 0.125f * (WMAX[t] + WMAX[64 + t] + WMAX[128 + t] + WMAX[192 + t] + __ldg(reatt + t));
            __syncthreads();
        }

        const uint32_t xlh = smb + XLH0 + buf * 32768;

        // ================= Phase 2: logits = ck^T * xl_hi =================
        float d2[4][4] = {};
        {
            const int arow = m0_2 + r8 + 8 * (i4 & 1);
            const int bro  = r8 + 8 * (i4 & 1);
            const int nch0 = (n0_2 >> 3) + (i4 >> 1);
            uint32_t ab = smb + CK_O + arow * 512;
#pragma unroll
            for (int s = 0; s < 16; s++) {
                uint32_t a[4], b0[4], b1[4];
                ldsm4(a, ab + (((s * 2 + (i4 >> 1)) ^ r8) << 4));
                uint32_t br = xlh + (s * 16 + bro) * 128;
                ldsm4t(b0, br + ((nch0 ^ r8) << 4));
                ldsm4t(b1, br + (((nch0 + 2) ^ r8) << 4));
                hmma(d2[0], a, b0); hmma(d2[1], a, b0 + 2);
                hmma(d2[2], a, b1); hmma(d2[3], a, b1 + 2);
            }
        }

        // ================= softmax (register-resident, 2 barriers) =================
        {
            float kb0 = KB[m0_2 + g8], kb1 = KB[m0_2 + g8 + 8];
            float cm[4][2];
#pragma unroll
            for (int ns = 0; ns < 4; ns++) {
                d2[ns][0] += kb0; d2[ns][1] += kb0;
                d2[ns][2] += kb1; d2[ns][3] += kb1;
                cm[ns][0] = fmaxf(d2[ns][0], d2[ns][2]);
                cm[ns][1] = fmaxf(d2[ns][1], d2[ns][3]);
            }
#pragma unroll
            for (int st = 4; st < 32; st <<= 1)
#pragma unroll
                for (int ns = 0; ns < 4; ns++) {
                    cm[ns][0] = fmaxf(cm[ns][0], __shfl_xor_sync(0xffffffffu, cm[ns][0], st));
                    cm[ns][1] = fmaxf(cm[ns][1], __shfl_xor_sync(0xffffffffu, cm[ns][1], st));
                }
            if (g8 == 0)
#pragma unroll
                for (int ns = 0; ns < 4; ns++) {
                    int n = n0_2 + ns * 8 + tid4 * 2;
                    *(float2*)(WMAX + (w >> 1) * 64 + n) = make_float2(cm[ns][0], cm[ns][1]);
                }
            __syncthreads();   // (1) WMAX partials visible

            float sm_[4][2];
            int k0r = m0_2 + g8;
#pragma unroll
            for (int ns = 0; ns < 4; ns++) {
                int n = n0_2 + ns * 8 + tid4 * 2;
                float2 p0 = *(float2*)(WMAX + n);
                float2 p1 = *(float2*)(WMAX + 64 + n);
                float2 p2 = *(float2*)(WMAX + 128 + n);
                float2 p3 = *(float2*)(WMAX + 192 + n);
                float c0 = fmaxf(fmaxf(p0.x, p1.x), fmaxf(p2.x, p3.x));
                float c1 = fmaxf(fmaxf(p0.y, p1.y), fmaxf(p2.y, p3.y));
                float e00 = __expf(d2[ns][0] - c0), e01 = __expf(d2[ns][1] - c1);
                float e10 = __expf(d2[ns][2] - c0), e11 = __expf(d2[ns][3] - c1);
                sm_[ns][0] = e00 + e10; sm_[ns][1] = e01 + e11;
                int off0 = k0r * 128 + (((n >> 3)) ^ g8) * 16 + (n & 7) * 2;
                int off1 = off0 + 8 * 128;
                *(uint32_t*)(smc + ATT_O + off0) = hpack(e00, e01);
                *(uint32_t*)(smc + ATT_O + off1) = hpack(e10, e11);
            }
#pragma unroll
            for (int st = 4; st < 32; st <<= 1)
#pragma unroll
                for (int ns = 0; ns < 4; ns++) {
                    sm_[ns][0] += __shfl_xor_sync(0xffffffffu, sm_[ns][0], st);
                    sm_[ns][1] += __shfl_xor_sync(0xffffffffu, sm_[ns][1], st);
                }
            if (g8 == 0)
#pragma unroll
                for (int ns = 0; ns < 4; ns++) {
                    int n = n0_2 + ns * 8 + tid4 * 2;
                    *(float2*)(WSUM + (w >> 1) * 64 + n) = make_float2(sm_[ns][0], sm_[ns][1]);
                }
            __syncthreads();   // (2) ATT + WSUM partials visible
            if (t < 64) INV[t] = 1.f / (WSUM[t] + WSUM[64 + t] + WSUM[128 + t] + WSUM[192 + t]);
            // INV published by the pre-epilogue barrier; phase3 gives the writer slack
        }

        // ---- prefetch next tile's x_l (overlaps phase3 + epilogue) ----
        const bool has_next = (g + 1 < start + cnt);
        if (has_next) {
            int gn = g + 1, bn = gn >> 8, hn = (gn & 255) << 6;
            const float4* xs = (const float4*)(x_l + (long)bn * 4194304 + hn);
#pragma unroll
            for (int i = 0; i < 16; i++) { int e = t + i * 256; pf[i] = __ldg(&xs[(long)(e >> 4) * 4096 + (e & 15)]); }
        }

        // ================= Phase 3: out-acc = cv * att =================
        float d3[2][8][4] = {};
        {
            const int bro = r8 + 8 * (i4 & 1);
            const int aro = r8 + 8 * (i4 & 1);
            uint32_t bb3 = smb + ATT_O;
#pragma unroll
            for (int ks = 0; ks < 4; ks++) {
                uint32_t bfr[4][4];
                uint32_t br = bb3 + (ks * 16 + bro) * 128;
#pragma unroll
                for (int nq = 0; nq < 4; nq++)
                    ldsm4t(bfr[nq], br + (((nq * 2 + (i4 >> 1)) ^ r8) << 4));
                int achk = ((ks * 2 + (i4 >> 1)) ^ r8) << 4;
#pragma unroll
                for (int ms = 0; ms < 2; ms++) {
                    uint32_t a[4];
                    ldsm4(a, smb + CV_O + (m0_3 + ms * 16 + aro) * 128 + achk);
#pragma unroll
                    for (int nq = 0; nq < 4; nq++) {
                        hmma(d3[ms][nq * 2], a, bfr[nq]);
                        hmma(d3[ms][nq * 2 + 1], a, bfr[nq] + 2);
                    }
                }
            }
        }
        __syncthreads();   // (3) publishes INV; orders phase3 ATT reads before next overwrite

        // ================= epilogue: residual + 1/sum, direct STG =================
        {
            const uint32_t xll = smb + XLL0 + buf * 32768;
            long gb = (long)b * 4194304 + hw0;
#pragma unroll
            for (int ms = 0; ms < 2; ms++) {
                int c0r = m0_3 + ms * 16 + g8, c1r = c0r + 8;
#pragma unroll
                for (int nq2 = 0; nq2 < 8; nq2++) {
                    int n = nq2 * 8 + tid4 * 2;
                    float2 iv = *(float2*)(INV + n);
                    int sw = ((n >> 3) ^ g8) << 4;
                    int o0 = c0r * 128 + sw + (n & 7) * 2;
                    int o1 = c1r * 128 + sw + (n & 7) * 2;
                    float2 h0 = hunpack(*(uint32_t*)(xlh + o0 - smb + (size_t)smc));
                    float2 l0 = hunpack(*(uint32_t*)(xll + o0 - smb + (size_t)smc));
                    float2 h1 = hunpack(*(uint32_t*)(xlh + o1 - smb + (size_t)smc));
                    float2 l1 = hunpack(*(uint32_t*)(xll + o1 - smb + (size_t)smc));
                    float2 r0, r1;
                    r0.x = h0.x + l0.x + d3[ms][nq2][0] * iv.x;
                    r0.y = h0.y + l0.y + d3[ms][nq2][1] * iv.y;
                    r1.x = h1.x + l1.x + d3[ms][nq2][2] * iv.x;
                    r1.y = h1.y + l1.y + d3[ms][nq2][3] * iv.y;
                    *(float2*)(out + gb + (long)c0r * 16384 + n) = r0;
                    *(float2*)(out + gb + (long)c1r * 16384 + n) = r1;
                }
            }
        }

        // ---- commit prefetched tile into the OTHER buffer ----
        if (has_next) {
            int nb = buf ^ 1;
#pragma unroll
            for (int i = 0; i < 16; i++) {
                int e = t + i * 256, c = e >> 4, n4 = e & 15;
                float4 v = pf[i];
                uint32_t h01, l01, h23, l23;
                hsplit2(v.x, v.y, h01, l01);
                hsplit2(v.z, v.w, h23, l23);
                int off = nb * 32768 + c * 128 + (((n4 >> 1) ^ (c & 7)) << 4) + (n4 & 1) * 8;
                *(uint2*)(smc + XLH0 + off) = make_uint2(h01, h23);
                *(uint2*)(smc + XLL0 + off) = make_uint2(l01, l23);
            }
        }
        __syncthreads();   // (4) commit visible before next phase2
        buf ^= 1;
    }
}

// ============================================================
extern "C" void kernel_launch(void* const* d_in, const int* in_sizes, int n_in,
                              void* d_out, int out_size)
{
    const float* x_h = (const float*)d_in[0];
    const float* x_l = (const float*)d_in[1];
    const float* bhg = (const float*)d_in[2];
    const float* bhb = (const float*)d_in[3];
    const float* bhm = (const float*)d_in[4];
    const float* bhv = (const float*)d_in[5];
    const float* kvw = (const float*)d_in[6];
    const float* kvb = (const float*)d_in[7];
    const float* blg = (const float*)d_in[8];
    const float* blb = (const float*)d_in[9];
    const float* blm = (const float*)d_in[10];
    const float* blv = (const float*)d_in[11];
    const float* reatt = (const float*)d_in[12];
    float* out = (float*)d_out;

    cudaFuncSetAttribute(kv_kernel,   cudaFuncAttributeMaxDynamicSharedMemorySize, 65536);
    cudaFuncSetAttribute(main_kernel, cudaFuncAttributeMaxDynamicSharedMemorySize, SMEMSZ);

    pool_kernel<<<1024, 256>>>(x_h, bhg, bhb, bhm, bhv);
    kv_kernel<<<dim3(8, 8), 256, 65536>>>(kvw, kvb);
    main_kernel<<<152, 256, SMEMSZ>>>(x_l, blg, blb, blm, blv, reatt, out);
}